// round 3
// baseline (speedup 1.0000x reference)
#include <cuda_runtime.h>
#include <cuda_bf16.h>

// ConvThreshold: scale-adaptive 5x5 Gaussian conv over ReLU(bev_map) + mask.
//   conv[b,y,x] = sum_{dy,dx in [-2,2]} relu(map[b,y+dy,x+dx]) * exp(-r2/(2*s^2+eps))
//   mask = conv >= 0.5
// r2 in {0,1,2,4,5,8}; all weights are powers of e1 = exp(-1/(2 s^2 + eps)).

#define BH 768
#define BW 768
#define NB 4

#define TX 32
#define TY 8

__global__ __launch_bounds__(TX * TY) void conv_threshold_kernel(
    const float* __restrict__ bev_map,
    const float* __restrict__ bev_scale,
    float* __restrict__ out_conv,
    float* __restrict__ out_mask)
{
    __shared__ float tile[TY + 4][TX + 4];

    const int bx = blockIdx.x * TX;
    const int by = blockIdx.y * TY;
    const int b  = blockIdx.z;
    const int tx = threadIdx.x;
    const int ty = threadIdx.y;

    const float* m = bev_map + (size_t)b * BH * BW;

    // Cooperative load of (TY+4) x (TX+4) tile with ReLU applied; zero halo OOB.
    for (int idx = ty * TX + tx; idx < (TY + 4) * (TX + 4); idx += TX * TY) {
        const int ly = idx / (TX + 4);
        const int lx = idx - ly * (TX + 4);
        const int gy = by + ly - 2;
        const int gx = bx + lx - 2;
        float v = 0.0f;
        if ((unsigned)gy < BH && (unsigned)gx < BW) v = __ldg(&m[gy * BW + gx]);
        tile[ly][lx] = fmaxf(v, 0.0f);
    }
    __syncthreads();

    const int gx = bx + tx;
    const int gy = by + ty;
    const size_t oidx = (size_t)b * BH * BW + (size_t)gy * BW + gx;

    const float s = bev_scale[oidx];
    const float inv = 1.0f / (2.0f * s * s + 1e-6f);

    // w(r2) = e1^r2 with e1 = exp(-inv). r2 in {0,1,2,4,5,8}.
    const float e1 = __expf(-inv);
    const float e2 = e1 * e1;
    const float e4 = e2 * e2;
    const float e5 = e4 * e1;
    const float e8 = e4 * e4;

    // weight LUT indexed by r2 (unused slots harmless)
    float wlut[9];
    wlut[0] = 1.0f; wlut[1] = e1; wlut[2] = e2; wlut[3] = 0.0f;
    wlut[4] = e4;   wlut[5] = e5; wlut[6] = 0.0f; wlut[7] = 0.0f;
    wlut[8] = e8;

    float acc = 0.0f;
#pragma unroll
    for (int dy = 0; dy < 5; dy++) {
#pragma unroll
        for (int dx = 0; dx < 5; dx++) {
            const int r2 = (dy - 2) * (dy - 2) + (dx - 2) * (dx - 2);
            acc = fmaf(tile[ty + dy][tx + dx], wlut[r2], acc);
        }
    }

    out_conv[oidx] = acc;
    out_mask[oidx] = (acc >= 0.5f) ? 1.0f : 0.0f;
}

extern "C" void kernel_launch(void* const* d_in, const int* in_sizes, int n_in,
                              void* d_out, int out_size)
{
    const float* bev_map   = (const float*)d_in[0];
    const float* bev_scale = (const float*)d_in[1];
    float* out = (float*)d_out;

    float* out_conv = out;
    float* out_mask = out + (size_t)NB * BH * BW;

    dim3 block(TX, TY);
    dim3 grid(BW / TX, BH / TY, NB);
    conv_threshold_kernel<<<grid, block>>>(bev_map, bev_scale, out_conv, out_mask);
}

// round 6
// speedup vs baseline: 1.4485x; 1.4485x over previous
#include <cuda_runtime.h>
#include <cuda_bf16.h>

// ConvThreshold: scale-adaptive 5x5 Gaussian conv over ReLU(bev_map) + mask.
//   conv[b,y,x] = sum relu(map[b,y+dy,x+dx]) * e1^r2,  e1 = exp(-1/(2 s^2 + eps))
//   mask = conv >= 0.5
// x4-vectorized: each thread produces 4 contiguous x pixels via LDS.128 reads.

#define BH 768
#define BW 768
#define NB 4

#define TX 32
#define TY 8
#define VEC 4
#define OW (TX * VEC)            // 128 output cols per block
// tile: rows TY+4, cols OW+8 padded to float4 grid starting at bx-4
#define TILE_W (OW + 8)          // 136 floats per row (544B, 16B-aligned)
#define TILE_H (TY + 4)          // 12 rows
#define TILE_W4 (TILE_W / 4)     // 34 float4 per row

__global__ __launch_bounds__(TX * TY) void conv_threshold_kernel(
    const float* __restrict__ bev_map,
    const float* __restrict__ bev_scale,
    float* __restrict__ out_conv,
    float* __restrict__ out_mask)
{
    __shared__ float tile[TILE_H][TILE_W];

    const int bx = blockIdx.x * OW;
    const int by = blockIdx.y * TY;
    const int b  = blockIdx.z;
    const int tx = threadIdx.x;
    const int ty = threadIdx.y;
    const int tid = ty * TX + tx;

    const float* m = bev_map + (size_t)b * BH * BW;

    // ---- cooperative tile load: [by-2, by+TY+2) x [bx-4, bx+OW+4), ReLU'd ----
    for (int idx = tid; idx < TILE_H * TILE_W4; idx += TX * TY) {
        const int ly  = idx / TILE_W4;
        const int lxv = idx - ly * TILE_W4;
        const int gy  = by + ly - 2;
        const int gx0 = bx - 4 + lxv * 4;

        float4 v;
        if ((unsigned)gy < BH && gx0 >= 0 && gx0 + 3 < BW) {
            v = *reinterpret_cast<const float4*>(&m[(size_t)gy * BW + gx0]);
        } else {
            const float* row = &m[(size_t)gy * BW];
            v.x = ((unsigned)gy < BH && (unsigned)(gx0 + 0) < BW) ? row[gx0 + 0] : 0.0f;
            v.y = ((unsigned)gy < BH && (unsigned)(gx0 + 1) < BW) ? row[gx0 + 1] : 0.0f;
            v.z = ((unsigned)gy < BH && (unsigned)(gx0 + 2) < BW) ? row[gx0 + 2] : 0.0f;
            v.w = ((unsigned)gy < BH && (unsigned)(gx0 + 3) < BW) ? row[gx0 + 3] : 0.0f;
        }
        v.x = fmaxf(v.x, 0.0f); v.y = fmaxf(v.y, 0.0f);
        v.z = fmaxf(v.z, 0.0f); v.w = fmaxf(v.w, 0.0f);
        *reinterpret_cast<float4*>(&tile[ly][lxv * 4]) = v;
    }
    __syncthreads();

    // ---- per-thread: 4 contiguous output pixels at gx..gx+3 ----
    const int gx = bx + tx * VEC;
    const int gy = by + ty;
    const size_t oidx = (size_t)b * BH * BW + (size_t)gy * BW + gx;

    const float4 s4 = *reinterpret_cast<const float4*>(&bev_scale[oidx]);

    // per-pixel weights (w = e1^r2, r2 in {0,1,2,4,5,8})
    float w1[VEC], w2[VEC], w4[VEC], w5[VEC], w8[VEC];
#pragma unroll
    for (int p = 0; p < VEC; p++) {
        const float s  = (p == 0) ? s4.x : (p == 1) ? s4.y : (p == 2) ? s4.z : s4.w;
        const float e1 = __expf(-1.0f / (2.0f * s * s + 1e-6f));
        const float e2 = e1 * e1;
        const float e4 = e2 * e2;
        w1[p] = e1; w2[p] = e2; w4[p] = e4; w5[p] = e4 * e1; w8[p] = e4 * e4;
    }

    float acc[VEC] = {0.0f, 0.0f, 0.0f, 0.0f};

    // Window for this thread's 4 pixels: tile cols [tx*4 .. tx*4+11] where
    // pixel p, tap dx reads tile col tx*4 + 2 + p + dx  (tile x-origin = bx-4).
    const int c0 = tx * VEC;
#pragma unroll
    for (int dy = 0; dy < 5; dy++) {
        const float4 a  = *reinterpret_cast<const float4*>(&tile[ty + dy][c0]);
        const float4 bq = *reinterpret_cast<const float4*>(&tile[ty + dy][c0 + 4]);
        const float4 c  = *reinterpret_cast<const float4*>(&tile[ty + dy][c0 + 8]);
        const int wy2 = (dy - 2) * (dy - 2);  // 4,1,0,1,4

        const float v[12] = {a.x, a.y, a.z, a.w, bq.x, bq.y, bq.z, bq.w,
                             c.x, c.y, c.z, c.w};
#pragma unroll
        for (int p = 0; p < VEC; p++) {
            // weights by |dx| for this row: r2 = wy2 + {4,1,0,1,4}
            float rw0, rw1, rw2;
            if (wy2 == 0)      { rw0 = w4[p]; rw1 = w1[p]; rw2 = 1.0f;  }
            else if (wy2 == 1) { rw0 = w5[p]; rw1 = w2[p]; rw2 = w1[p]; }
            else               { rw0 = w8[p]; rw1 = w5[p]; rw2 = w4[p]; }
            acc[p] = fmaf(v[2 + p + 0], rw0, acc[p]);
            acc[p] = fmaf(v[2 + p + 1], rw1, acc[p]);
            acc[p] = fmaf(v[2 + p + 2], rw2, acc[p]);
            acc[p] = fmaf(v[2 + p + 3], rw1, acc[p]);
            acc[p] = fmaf(v[2 + p + 4], rw0, acc[p]);
        }
    }

    float4 conv4 = make_float4(acc[0], acc[1], acc[2], acc[3]);
    float4 mask4 = make_float4(acc[0] >= 0.5f ? 1.0f : 0.0f,
                               acc[1] >= 0.5f ? 1.0f : 0.0f,
                               acc[2] >= 0.5f ? 1.0f : 0.0f,
                               acc[3] >= 0.5f ? 1.0f : 0.0f);
    *reinterpret_cast<float4*>(&out_conv[oidx]) = conv4;
    *reinterpret_cast<float4*>(&out_mask[oidx]) = mask4;
}

extern "C" void kernel_launch(void* const* d_in, const int* in_sizes, int n_in,
                              void* d_out, int out_size)
{
    const float* bev_map   = (const float*)d_in[0];
    const float* bev_scale = (const float*)d_in[1];
    float* out = (float*)d_out;

    float* out_conv = out;
    float* out_mask = out + (size_t)NB * BH * BW;

    dim3 block(TX, TY);
    dim3 grid(BW / OW, BH / TY, NB);
    conv_threshold_kernel<<<grid, block>>>(bev_map, bev_scale, out_conv, out_mask);
}

// round 7
// speedup vs baseline: 1.5115x; 1.0435x over previous
#include <cuda_runtime.h>
#include <cuda_bf16.h>

// ConvThreshold: scale-adaptive 5x5 Gaussian conv over ReLU(bev_map) + mask.
//   conv[b,y,x] = sum relu(map[y+dy,x+dx]) * e1^(dy^2+dx^2),  e1 = exp(-1/(2 s^2+eps))
// Separable weights: w = e1^dy2 * e1^dx2 -> per-row sum with {e4,e1,1}, then
// column weight {e4,e1,1}. Each thread: 4 x-pixels x 2 y-rows, LDS.128 reads.

#define BH 768
#define BW 768
#define NB 4

#define TX 32
#define TY 8
#define VEC 4
#define RPT 2                    // output rows per thread
#define OW (TX * VEC)            // 128 output cols per block
#define OH (TY * RPT)            // 16 output rows per block
#define TILE_W (OW + 8)          // 136 floats (x-origin = bx-4), 16B aligned
#define TILE_H (OH + 4)          // 20 rows   (y-origin = by-2)
#define TILE_W4 (TILE_W / 4)     // 34

__global__ __launch_bounds__(TX * TY) void conv_threshold_kernel(
    const float* __restrict__ bev_map,
    const float* __restrict__ bev_scale,
    float* __restrict__ out_conv,
    float* __restrict__ out_mask)
{
    __shared__ float tile[TILE_H][TILE_W];

    const int bx = blockIdx.x * OW;
    const int by = blockIdx.y * OH;
    const int b  = blockIdx.z;
    const int tx = threadIdx.x;
    const int ty = threadIdx.y;
    const int tid = ty * TX + tx;

    const float* m = bev_map + (size_t)b * BH * BW;

    // ---- cooperative tile load: [by-2, by+OH+2) x [bx-4, bx+OW+4), ReLU'd ----
    for (int idx = tid; idx < TILE_H * TILE_W4; idx += TX * TY) {
        const int ly  = idx / TILE_W4;
        const int lxv = idx - ly * TILE_W4;
        const int gy  = by + ly - 2;
        const int gx0 = bx - 4 + lxv * 4;

        float4 v;
        if ((unsigned)gy < BH && gx0 >= 0 && gx0 + 3 < BW) {
            v = *reinterpret_cast<const float4*>(&m[(size_t)gy * BW + gx0]);
        } else {
            const float* row = &m[(size_t)gy * BW];
            v.x = ((unsigned)gy < BH && (unsigned)(gx0 + 0) < BW) ? row[gx0 + 0] : 0.0f;
            v.y = ((unsigned)gy < BH && (unsigned)(gx0 + 1) < BW) ? row[gx0 + 1] : 0.0f;
            v.z = ((unsigned)gy < BH && (unsigned)(gx0 + 2) < BW) ? row[gx0 + 2] : 0.0f;
            v.w = ((unsigned)gy < BH && (unsigned)(gx0 + 3) < BW) ? row[gx0 + 3] : 0.0f;
        }
        v.x = fmaxf(v.x, 0.0f); v.y = fmaxf(v.y, 0.0f);
        v.z = fmaxf(v.z, 0.0f); v.w = fmaxf(v.w, 0.0f);
        *reinterpret_cast<float4*>(&tile[ly][lxv * 4]) = v;
    }
    __syncthreads();

    // ---- per-thread: 4 x-pixels (gx..gx+3) x 2 y-rows (oy0, oy0+1) ----
    const int gx  = bx + tx * VEC;
    const int oy0 = by + ty * RPT;
    const size_t obase = (size_t)b * BH * BW + (size_t)oy0 * BW + gx;

    // per-(row,pixel) weights e1 = exp(-1/(2 s^2 + eps)), e4 = e1^4
    float e1w[RPT][VEC], e4w[RPT][VEC];
#pragma unroll
    for (int o = 0; o < RPT; o++) {
        const float4 s4 = *reinterpret_cast<const float4*>(
            &bev_scale[obase + (size_t)o * BW]);
#pragma unroll
        for (int p = 0; p < VEC; p++) {
            const float s = (p == 0) ? s4.x : (p == 1) ? s4.y : (p == 2) ? s4.z : s4.w;
            const float e1 = __expf(-1.0f / (2.0f * s * s + 1e-6f));
            const float e2 = e1 * e1;
            e1w[o][p] = e1;
            e4w[o][p] = e2 * e2;
        }
    }

    float acc[RPT][VEC] = {{0.0f, 0.0f, 0.0f, 0.0f}, {0.0f, 0.0f, 0.0f, 0.0f}};

    const int c0 = tx * VEC;       // window cols [c0 .. c0+11]; pixel p tap dx -> v[2+p+dx]
    const int r0 = ty * RPT;       // tile row of out row0's dy=0 tap

#pragma unroll
    for (int r = 0; r < 5 + RPT - 1; r++) {   // 6 tile rows
        const float4 a  = *reinterpret_cast<const float4*>(&tile[r0 + r][c0]);
        const float4 bq = *reinterpret_cast<const float4*>(&tile[r0 + r][c0 + 4]);
        const float4 c  = *reinterpret_cast<const float4*>(&tile[r0 + r][c0 + 8]);
        const float v[12] = {a.x, a.y, a.z, a.w, bq.x, bq.y, bq.z, bq.w,
                             c.x, c.y, c.z, c.w};

        // weight-independent x-pair sums, shared by both output rows
        float a04[VEC], a13[VEC], a2[VEC];
#pragma unroll
        for (int p = 0; p < VEC; p++) {
            a04[p] = v[2 + p] + v[6 + p];
            a13[p] = v[3 + p] + v[5 + p];
            a2[p]  = v[4 + p];
        }

#pragma unroll
        for (int o = 0; o < RPT; o++) {
            const int k = r - o;               // tap index for output row o
            if (k >= 0 && k <= 4) {
                const int ady = (k < 2) ? (2 - k) : (k - 2);   // |dy| in {0,1,2}
#pragma unroll
                for (int p = 0; p < VEC; p++) {
                    const float rs = fmaf(e4w[o][p], a04[p],
                                     fmaf(e1w[o][p], a13[p], a2[p]));
                    if (ady == 0)      acc[o][p] += rs;
                    else if (ady == 1) acc[o][p] = fmaf(rs, e1w[o][p], acc[o][p]);
                    else               acc[o][p] = fmaf(rs, e4w[o][p], acc[o][p]);
                }
            }
        }
    }

#pragma unroll
    for (int o = 0; o < RPT; o++) {
        float4 conv4 = make_float4(acc[o][0], acc[o][1], acc[o][2], acc[o][3]);
        float4 mask4 = make_float4(acc[o][0] >= 0.5f ? 1.0f : 0.0f,
                                   acc[o][1] >= 0.5f ? 1.0f : 0.0f,
                                   acc[o][2] >= 0.5f ? 1.0f : 0.0f,
                                   acc[o][3] >= 0.5f ? 1.0f : 0.0f);
        *reinterpret_cast<float4*>(&out_conv[obase + (size_t)o * BW]) = conv4;
        *reinterpret_cast<float4*>(&out_mask[obase + (size_t)o * BW]) = mask4;
    }
}

extern "C" void kernel_launch(void* const* d_in, const int* in_sizes, int n_in,
                              void* d_out, int out_size)
{
    const float* bev_map   = (const float*)d_in[0];
    const float* bev_scale = (const float*)d_in[1];
    float* out = (float*)d_out;

    float* out_conv = out;
    float* out_mask = out + (size_t)NB * BH * BW;

    dim3 block(TX, TY);
    dim3 grid(BW / OW, BH / OH, NB);
    conv_threshold_kernel<<<grid, block>>>(bev_map, bev_scale, out_conv, out_mask);
}